// round 8
// baseline (speedup 1.0000x reference)
#include <cuda_runtime.h>
#include <cuda_fp16.h>
#include <cstdint>

typedef unsigned long long ull;
typedef unsigned int u32;

// ---------------- global scratch (static, no allocs) ----------------
// E fragment image: granule g = ks (0..7) -> 8192 u32 (32KB)
//   granule: [nblk(64)][8 codes -> q(8)][jj(4)][bh_s0, bh_s1, bl_s0, bl_s1]
//   (nblk = code>>3, q = code&7; uint4 per lane = both hi and lo B fragments)
__device__ __align__(16) u32 g_Eimg2[65536];     // 256KB
__device__ float g_hhalf[512];                   // 0.5*||e_k||^2

__device__ __forceinline__ u32 packsplit_hi(float v0, float v1, float& r0, float& r1) {
    __half h0 = __float2half_rn(v0), h1 = __float2half_rn(v1);
    r0 = v0 - __half2float(h0);
    r1 = v1 - __half2float(h1);
    return (u32)__half_as_ushort(h0) | ((u32)__half_as_ushort(h1) << 16);
}
__device__ __forceinline__ u32 pack_lo(float r0, float r1) {
    __half l0 = __float2half_rn(r0), l1 = __float2half_rn(r1);
    return (u32)__half_as_ushort(l0) | ((u32)__half_as_ushort(l1) << 16);
}
__device__ __forceinline__ unsigned fkey(float f) {   // monotonic float->uint
    unsigned u = __float_as_uint(f);
    return (u & 0x80000000u) ? ~u : (u | 0x80000000u);
}
__device__ __forceinline__ void mma16(float* c, u32 a0, u32 a1, u32 a2, u32 a3,
                                      u32 b0, u32 b1) {
    asm("mma.sync.aligned.m16n8k16.row.col.f32.f16.f16.f32 "
        "{%0,%1,%2,%3}, {%4,%5,%6,%7}, {%8,%9}, {%0,%1,%2,%3};"
        : "+f"(c[0]), "+f"(c[1]), "+f"(c[2]), "+f"(c[3])
        : "r"(a0), "r"(a1), "r"(a2), "r"(a3), "r"(b0), "r"(b1));
}
__device__ __forceinline__ u32 smem_u32(const void* p) {
    u32 a;
    asm("{ .reg .u64 t; cvta.to.shared.u64 t, %1; cvt.u32.u64 %0, t; }" : "=r"(a) : "l"(p));
    return a;
}
__device__ __forceinline__ void cp16(u32 dst, const void* src) {
    asm volatile("cp.async.cg.shared.global [%0], [%1], 16;" :: "r"(dst), "l"(src));
}
#define CP_COMMIT() asm volatile("cp.async.commit_group;" ::: "memory")
#define CP_WAIT0()  asm volatile("cp.async.wait_group 0;" ::: "memory")

// ---------------- prep: build fp16-split E image + half-norms ----------------
__global__ void vq_prep(const float* __restrict__ emb) {
    int t = blockIdx.x * blockDim.x + threadIdx.x;
    int nt = gridDim.x * blockDim.x;
    for (int i = t; i < 512 * 64; i += nt) {       // (code, kpair)
        int code = i >> 6, p = i & 63;
        float v0 = emb[code * 128 + 2 * p], v1 = emb[code * 128 + 2 * p + 1];
        float r0, r1;
        u32 hi = packsplit_hi(v0, v1, r0, r1);
        u32 lo = pack_lo(r0, r1);
        int ks = p >> 3, j = p & 7, jj = j & 3, s = j >> 2;
        int nblk = code >> 3, q = code & 7;
        int base = ks * 8192 + nblk * 128 + q * 16 + jj * 4;
        g_Eimg2[base + s] = hi;          // bh slots 0,1
        g_Eimg2[base + 2 + s] = lo;      // bl slots 2,3
    }
    if (t < 512) {
        const float* row = emb + t * 128;
        float s = 0.f;
        #pragma unroll 4
        for (int c = 0; c < 128; ++c) { float v = row[c]; s += v * v; }
        g_hhalf[t] = 0.5f * s;
    }
}

// ---------------- main kernel ----------------
// SMEM u32 offsets (64-px CTA):
//  A region: 64 rows x 144 u32 (128 data + 16 pad) -> 0 .. 9216
//    row col for (ks,jj): ks*16 + jj*4 + [ah_s0, ah_s1, al_s0, al_s1]
//  E buffers: 2 x 8192   -> 9216 .. 25600
//  hh[512] floats        -> 25600 .. 26112
//  bestS[64] ull         -> 26112 .. 26240
#define ASTRIDE 144
#define EOFF   9216
#define HHOFF  25600
#define BESTU  26112
#define SMEM_BYTES (26240 * 4)
#define QS_STRIDE 68

__global__ __launch_bounds__(256, 1)
void vq_mma_kernel(const float* __restrict__ z, const float* __restrict__ emb,
                   float* __restrict__ out) {
    extern __shared__ float SMF[];
    u32* ZU = (u32*)SMF;
    float* hh_s = SMF + HHOFF;
    ull* bestS = (ull*)(SMF + BESTU);

    const int tid = threadIdx.x;
    const int cg = tid >> 5, lane = tid & 31;      // warp = code group (64 codes)
    const int jj = lane & 3, q = lane >> 2;
    const int b = blockIdx.x >> 6;
    const int p0 = (blockIdx.x & 63) << 6;         // 64-px tile

    const float* zb = z + (size_t)b * 128 * 4096 + p0;

    hh_s[tid] = g_hhalf[tid];
    hh_s[tid + 256] = g_hhalf[tid + 256];
    if (tid < 64) bestS[tid] = ~0ull;

    // ---- Z producer: fp16-split 64px x 128k into packed A fragments ----
    {
        int px = tid & 63, kg = tid >> 6;          // 4 groups x 16 kpairs
        u32* Arow = ZU + px * ASTRIDE;
        #pragma unroll
        for (int pi = 0; pi < 16; ++pi) {
            int p = kg * 16 + pi;
            float v0 = zb[(size_t)(2 * p) * 4096 + px];
            float v1 = zb[(size_t)(2 * p + 1) * 4096 + px];
            float r0, r1;
            u32 hi = packsplit_hi(v0, v1, r0, r1);
            u32 lo = pack_lo(r0, r1);
            int ks = p >> 3, j = p & 7;
            int o = ks * 16 + (j & 3) * 4 + (j >> 2);
            Arow[o] = hi;
            Arow[o + 2] = lo;
        }
    }

    // ---- cp.async double-buffered granule pipeline (32KB granules) ----
    const u32 sb = smem_u32(SMF);
    auto issue = [&](int g) {      // granule g (8192 u32) -> buffer g&1
        u32 dst = sb + (u32)(EOFF + (g & 1) * 8192) * 4;
        const u32* src = g_Eimg2 + (size_t)g * 8192;
        #pragma unroll
        for (int i = 0; i < 8; ++i)
            cp16(dst + (u32)(tid + i * 256) * 16, src + (size_t)(tid + i * 256) * 4);
        CP_COMMIT();
    };
    issue(0);

    float acc[4][8][4];
    #pragma unroll
    for (int m = 0; m < 4; ++m)
        #pragma unroll
        for (int n = 0; n < 8; ++n)
            #pragma unroll
            for (int r = 0; r < 4; ++r) acc[m][n][r] = 0.f;

    for (int ks = 0; ks < 8; ++ks) {
        CP_WAIT0();
        __syncthreads();                           // publish ks; ks-1 readers done
        if (ks + 1 < 8) issue(ks + 1);             // overlaps mma below

        uint4 A[4][2];
        const int ao = ks * 16 + jj * 4;
        #pragma unroll
        for (int m = 0; m < 4; ++m) {
            A[m][0] = *(const uint4*)(ZU + (m * 16 + q) * ASTRIDE + ao);
            A[m][1] = *(const uint4*)(ZU + (m * 16 + q + 8) * ASTRIDE + ao);
        }
        const u32* ebuf = ZU + EOFF + (ks & 1) * 8192 + cg * 1024 + lane * 4;
        #pragma unroll
        for (int n = 0; n < 8; ++n) {
            uint4 B = *(const uint4*)(ebuf + n * 128);   // [bh.x bh.y bl.x bl.y]
            #pragma unroll
            for (int m = 0; m < 4; ++m) {
                mma16(acc[m][n], A[m][0].x, A[m][1].x, A[m][0].y, A[m][1].y, B.x, B.y);
                mma16(acc[m][n], A[m][0].z, A[m][1].z, A[m][0].w, A[m][1].w, B.x, B.y);
                mma16(acc[m][n], A[m][0].x, A[m][1].x, A[m][0].y, A[m][1].y, B.z, B.w);
            }
        }
    }

    // ---- per-pixel argmin over this warp's 64 codes: dist = 0.5||e||^2 - z.e ----
    #pragma unroll
    for (int m = 0; m < 4; ++m) {
        ull bA = ~0ull, bB = ~0ull;
        #pragma unroll
        for (int n = 0; n < 8; ++n) {
            int c = cg * 64 + 8 * n + 2 * jj;
            float hc0 = hh_s[c], hc1 = hh_s[c + 1];
            ull kA0 = ((ull)fkey(hc0 - acc[m][n][0]) << 32) | (u32)c;
            ull kA1 = ((ull)fkey(hc1 - acc[m][n][1]) << 32) | (u32)(c + 1);
            ull kB0 = ((ull)fkey(hc0 - acc[m][n][2]) << 32) | (u32)c;
            ull kB1 = ((ull)fkey(hc1 - acc[m][n][3]) << 32) | (u32)(c + 1);
            ull a  = kA0 < kA1 ? kA0 : kA1;
            ull bb = kB0 < kB1 ? kB0 : kB1;
            if (a < bA) bA = a;
            if (bb < bB) bB = bb;
        }
        #pragma unroll
        for (int d = 1; d <= 2; d <<= 1) {
            ull oa = __shfl_xor_sync(0xffffffffu, bA, d);
            ull ob = __shfl_xor_sync(0xffffffffu, bB, d);
            if (oa < bA) bA = oa;
            if (ob < bB) bB = ob;
        }
        if (jj == 0) {
            atomicMin(&bestS[m * 16 + q], bA);
            atomicMin(&bestS[m * 16 + q + 8], bB);
        }
    }

    __syncthreads();   // bestS final; A region reusable as gather staging

    // ---- gather winning rows into Qs[c][px], then coalesced write ----
    {
        int px = tid >> 2, qu = tid & 3;
        u32 idx = (u32)bestS[px];
        const float* er = emb + (size_t)idx * 128 + 32 * qu;
        float* Qs = SMF;
        #pragma unroll
        for (int i = 0; i < 8; ++i) {
            float4 v = *(const float4*)(er + 4 * i);
            int c = 32 * qu + 4 * i;
            Qs[(c + 0) * QS_STRIDE + px] = v.x;
            Qs[(c + 1) * QS_STRIDE + px] = v.y;
            Qs[(c + 2) * QS_STRIDE + px] = v.z;
            Qs[(c + 3) * QS_STRIDE + px] = v.w;
        }
    }
    __syncthreads();
    {
        int r = tid >> 1, half = tid & 1;          // 128 ch x 2 halves of 32px
        float* orow = out + (size_t)b * 128 * 4096 + (size_t)r * 4096 + p0 + 32 * half;
        const float* qrow = SMF + r * QS_STRIDE + 32 * half;
        #pragma unroll
        for (int i = 0; i < 8; ++i)
            *(float4*)(orow + 4 * i) = *(const float4*)(qrow + 4 * i);
    }
}

extern "C" void kernel_launch(void* const* d_in, const int* in_sizes, int n_in,
                              void* d_out, int out_size) {
    const float* z   = (const float*)d_in[0];   // (32,128,64,64) fp32
    const float* emb = (const float*)d_in[1];   // (512,128) fp32
    float* out = (float*)d_out;

    cudaFuncSetAttribute(vq_mma_kernel,
                         cudaFuncAttributeMaxDynamicSharedMemorySize, SMEM_BYTES);

    vq_prep<<<64, 256>>>(emb);
    vq_mma_kernel<<<2048, 256, SMEM_BYTES>>>(z, emb, out);
}

// round 9
// speedup vs baseline: 1.2878x; 1.2878x over previous
#include <cuda_runtime.h>
#include <cuda_fp16.h>
#include <cstdint>

typedef unsigned long long ull;
typedef unsigned int u32;

// ---------------- global scratch (static, no allocs) ----------------
// Bh fragment image: granule g = h*8+ks -> 2048 u32 (8KB); 16 granules = 128KB
//   granule: [nblk(32)][q(8)][jj(4)][s(2)]; code = h*256+nblk*8+q, kpair = 8ks+jj+4s
__device__ __align__(16) u32 g_EimgH[32768];
__device__ float g_hhalf[512];     // 0.5*||e_c||^2 (fp32)
__device__ int g_emax2bits;        // max ||e_c||^2 as float bits (zero-init)

#define KEPS 1.25e-3f
#define CMAX 16

__device__ __forceinline__ u32 packsplit_hi(float v0, float v1, float& r0, float& r1) {
    __half h0 = __float2half_rn(v0), h1 = __float2half_rn(v1);
    r0 = v0 - __half2float(h0);
    r1 = v1 - __half2float(h1);
    return (u32)__half_as_ushort(h0) | ((u32)__half_as_ushort(h1) << 16);
}
__device__ __forceinline__ u32 pack_lo(float r0, float r1) {
    __half l0 = __float2half_rn(r0), l1 = __float2half_rn(r1);
    return (u32)__half_as_ushort(l0) | ((u32)__half_as_ushort(l1) << 16);
}
__device__ __forceinline__ unsigned fkey(float f) {   // monotonic float->uint
    unsigned u = __float_as_uint(f);
    return (u & 0x80000000u) ? ~u : (u | 0x80000000u);
}
__device__ __forceinline__ float unfkey(u32 k) {
    u32 u = (k & 0x80000000u) ? (k & 0x7fffffffu) : ~k;
    return __uint_as_float(u);
}
__device__ __forceinline__ void mma16(float* c, u32 a0, u32 a1, u32 a2, u32 a3,
                                      u32 b0, u32 b1) {
    asm("mma.sync.aligned.m16n8k16.row.col.f32.f16.f16.f32 "
        "{%0,%1,%2,%3}, {%4,%5,%6,%7}, {%8,%9}, {%0,%1,%2,%3};"
        : "+f"(c[0]), "+f"(c[1]), "+f"(c[2]), "+f"(c[3])
        : "r"(a0), "r"(a1), "r"(a2), "r"(a3), "r"(b0), "r"(b1));
}
__device__ __forceinline__ u32 smem_u32(const void* p) {
    u32 a;
    asm("{ .reg .u64 t; cvta.to.shared.u64 t, %1; cvt.u32.u64 %0, t; }" : "=r"(a) : "l"(p));
    return a;
}
__device__ __forceinline__ void cp16(u32 dst, const void* src) {
    asm volatile("cp.async.cg.shared.global [%0], [%1], 16;" :: "r"(dst), "l"(src));
}
#define CP_COMMIT() asm volatile("cp.async.commit_group;" ::: "memory")
#define CP_WAIT0()  asm volatile("cp.async.wait_group 0;" ::: "memory")

// ---------------- prep: Bh-only fragment image + norms ----------------
__global__ void vq_prep(const float* __restrict__ emb) {
    int t = blockIdx.x * blockDim.x + threadIdx.x;
    int nt = gridDim.x * blockDim.x;
    for (int i = t; i < 512 * 64; i += nt) {       // (code, kpair)
        int code = i >> 6, p = i & 63;
        float v0 = emb[code * 128 + 2 * p], v1 = emb[code * 128 + 2 * p + 1];
        float r0, r1;
        u32 hi = packsplit_hi(v0, v1, r0, r1);
        int ks = p >> 3, j = p & 7, jj = j & 3, s = j >> 2;
        int h = code >> 8, nblk = (code >> 3) & 31, q = code & 7;
        g_EimgH[(h * 8 + ks) * 2048 + nblk * 64 + 8 * q + 2 * jj + s] = hi;
    }
    if (t < 512) {
        const float* row = emb + t * 128;
        float s2 = 0.f;
        #pragma unroll 4
        for (int c = 0; c < 128; ++c) { float v = row[c]; s2 += v * v; }
        g_hhalf[t] = 0.5f * s2;
        atomicMax(&g_emax2bits, __float_as_int(s2));
    }
}

// ---------------- main kernel ----------------
// SMEM u32 offsets (64-px CTA):
#define ZHOFF  0          // 64 x 72
#define ZLOFF  4608       // 64 x 72
#define EBOFF  9216       // 2 x 2048
#define HHOFF  13312      // 512 floats
#define ZNOFF  13824      // 64 floats
#define BSTOFF 13888      // 64 ull (128 u32)
#define CDOFF  14016      // 64 x 16 floats
#define CCOFF  15040      // 64 x 16 u32
#define CNTOFF 16064      // 64 u32
#define FIOFF  16128      // 64 u32
#define SMEM_BYTES (16192 * 4)
#define QS_STRIDE 68

__device__ __forceinline__ float rescore_dot(const u32* __restrict__ ZH,
                                             const u32* __restrict__ ZL,
                                             const float* __restrict__ emb,
                                             int px, int cc, int lane) {
    int p0 = 2 * lane, p1 = p0 + 1;
    int col0 = (p0 >> 3) * 8 + 2 * (p0 & 3) + ((p0 >> 2) & 1);
    int col1 = (p1 >> 3) * 8 + 2 * (p1 & 3) + ((p1 >> 2) & 1);
    const u32* zh = ZH + px * 72;
    const u32* zl = ZL + px * 72;
    float2 a0 = __half22float2(*(const __half2*)&zh[col0]);
    float2 b0 = __half22float2(*(const __half2*)&zl[col0]);
    float2 a1 = __half22float2(*(const __half2*)&zh[col1]);
    float2 b1 = __half22float2(*(const __half2*)&zl[col1]);
    float4 e = *(const float4*)(emb + (size_t)cc * 128 + 4 * lane);
    float part = (a0.x + b0.x) * e.x + (a0.y + b0.y) * e.y
               + (a1.x + b1.x) * e.z + (a1.y + b1.y) * e.w;
    #pragma unroll
    for (int d = 16; d; d >>= 1) part += __shfl_xor_sync(0xffffffffu, part, d);
    return part;
}

__global__ __launch_bounds__(256, 2)
void vq_mma_kernel(const float* __restrict__ z, const float* __restrict__ emb,
                   float* __restrict__ out) {
    extern __shared__ float SMF[];
    u32* ZU = (u32*)SMF;
    const u32* ZH = ZU + ZHOFF;
    const u32* ZL = ZU + ZLOFF;
    float* hh_s = SMF + HHOFF;
    float* znorm = SMF + ZNOFF;
    ull* bestS = (ull*)(SMF + BSTOFF);
    float* candD = SMF + CDOFF;
    u32* candC = ZU + CCOFF;
    u32* cnt_s = ZU + CNTOFF;
    u32* fidx = ZU + FIOFF;

    const int tid = threadIdx.x;
    const int wid = tid >> 5, lane = tid & 31;
    const int jj = lane & 3, q = lane >> 2;
    const int pg = wid & 1, cg = wid >> 1;          // 2 px-groups x 4 code-groups
    const int px0 = pg << 5;
    const int b = blockIdx.x >> 6;
    const int p0 = (blockIdx.x & 63) << 6;          // 64-px tile

    const float* zb = z + (size_t)b * 128 * 4096 + p0;

    hh_s[tid] = g_hhalf[tid];
    hh_s[tid + 256] = g_hhalf[tid + 256];
    if (tid < 64) { bestS[tid] = ~0ull; znorm[tid] = 0.f; cnt_s[tid] = 0u; }
    __syncthreads();

    // ---- Z producer: fp16-split 64px x 128k into hi/lo planes + ||z||^2 ----
    {
        int px = tid & 63, kg = tid >> 6;           // 4 groups x 16 kpairs
        u32* Zh = ZU + ZHOFF + px * 72;
        u32* Zl = ZU + ZLOFF + px * 72;
        float s = 0.f;
        #pragma unroll
        for (int pi = 0; pi < 16; ++pi) {
            int p = kg * 16 + pi;
            float v0 = zb[(size_t)(2 * p) * 4096 + px];
            float v1 = zb[(size_t)(2 * p + 1) * 4096 + px];
            float r0, r1;
            u32 hi = packsplit_hi(v0, v1, r0, r1);
            u32 lo = pack_lo(r0, r1);
            int col = (p >> 3) * 8 + 2 * (p & 3) + ((p >> 2) & 1);
            Zh[col] = hi;
            Zl[col] = lo;
            s += v0 * v0 + v1 * v1;
        }
        atomicAdd(&znorm[px], s);
    }

    // ---- cp.async double-buffered Bh granule pipeline (8KB granules) ----
    const u32 sb = smem_u32(SMF);
    auto issue = [&](int g) {
        u32 dst = sb + (u32)(EBOFF + (g & 1) * 2048) * 4;
        const u32* src = g_EimgH + (size_t)g * 2048;
        cp16(dst + (u32)tid * 16, src + (size_t)tid * 4);
        cp16(dst + (u32)(tid + 256) * 16, src + (size_t)(tid + 256) * 4);
        CP_COMMIT();
    };
    issue(0);

    const float emax2 = __int_as_float(g_emax2bits);

    for (int h = 0; h < 2; ++h) {
        float acc[2][8][4];
        #pragma unroll
        for (int m = 0; m < 2; ++m)
            #pragma unroll
            for (int n = 0; n < 8; ++n)
                #pragma unroll
                for (int r = 0; r < 4; ++r) acc[m][n][r] = 0.f;

        for (int ks = 0; ks < 8; ++ks) {
            int g = h * 8 + ks;
            CP_WAIT0();
            __syncthreads();                        // publish g; g-1 readers done
            if (g + 1 < 16) issue(g + 1);           // overlaps mma below

            const int ao = ks * 8 + 2 * jj;
            uint2 a0 = *(const uint2*)(ZH + (px0 + q) * 72 + ao);
            uint2 a1 = *(const uint2*)(ZH + (px0 + q + 8) * 72 + ao);
            uint2 a2 = *(const uint2*)(ZH + (px0 + q + 16) * 72 + ao);
            uint2 a3 = *(const uint2*)(ZH + (px0 + q + 24) * 72 + ao);
            const u32* ebuf = ZU + EBOFF + (g & 1) * 2048 + cg * 512 + 2 * lane;
            #pragma unroll
            for (int n = 0; n < 8; ++n) {
                uint2 B = *(const uint2*)(ebuf + n * 64);
                mma16(acc[0][n], a0.x, a1.x, a0.y, a1.y, B.x, B.y);
                mma16(acc[1][n], a2.x, a3.x, a2.y, a3.y, B.x, B.y);
            }
        }

        // ---- phase-1 epilogue: argmin + candidate collection ----
        #pragma unroll
        for (int m = 0; m < 2; ++m) {
            int rowA = px0 + 16 * m + q, rowB = rowA + 8;
            ull bA = ~0ull, bB = ~0ull;
            #pragma unroll
            for (int n = 0; n < 8; ++n) {
                int c = h * 256 + cg * 64 + 8 * n + 2 * jj;
                float hc0 = hh_s[c], hc1 = hh_s[c + 1];
                ull kA0 = ((ull)fkey(hc0 - acc[m][n][0]) << 32) | (u32)c;
                ull kA1 = ((ull)fkey(hc1 - acc[m][n][1]) << 32) | (u32)(c + 1);
                ull kB0 = ((ull)fkey(hc0 - acc[m][n][2]) << 32) | (u32)c;
                ull kB1 = ((ull)fkey(hc1 - acc[m][n][3]) << 32) | (u32)(c + 1);
                ull a  = kA0 < kA1 ? kA0 : kA1;
                ull bb = kB0 < kB1 ? kB0 : kB1;
                if (a < bA) bA = a;
                if (bb < bB) bB = bb;
            }
            #pragma unroll
            for (int d = 1; d <= 2; d <<= 1) {
                ull oa = __shfl_xor_sync(0xffffffffu, bA, d);
                ull ob = __shfl_xor_sync(0xffffffffu, bB, d);
                if (oa < bA) bA = oa;
                if (ob < bB) bB = ob;
            }
            // thresholds vs best-known (own warp min vs current global; only loosens)
            ull curA = *(volatile ull*)&bestS[rowA];
            ull curB = *(volatile ull*)&bestS[rowB];
            float MA = KEPS * sqrtf(znorm[rowA] * emax2);
            float MB = KEPS * sqrtf(znorm[rowB] * emax2);
            float thA = unfkey((u32)((bA < curA ? bA : curA) >> 32)) + 2.f * MA;
            float thB = unfkey((u32)((bB < curB ? bB : curB) >> 32)) + 2.f * MB;
            if (jj == 0) {
                atomicMin(&bestS[rowA], bA);
                atomicMin(&bestS[rowB], bB);
            }
            #pragma unroll
            for (int n = 0; n < 8; ++n) {
                int c = h * 256 + cg * 64 + 8 * n + 2 * jj;
                float hc0 = hh_s[c], hc1 = hh_s[c + 1];
                float d0A = hc0 - acc[m][n][0], d1A = hc1 - acc[m][n][1];
                float d0B = hc0 - acc[m][n][2], d1B = hc1 - acc[m][n][3];
                if (d0A <= thA) { u32 s = atomicAdd(&cnt_s[rowA], 1u); if (s < CMAX) { candD[rowA * CMAX + s] = d0A; candC[rowA * CMAX + s] = (u32)c; } }
                if (d1A <= thA) { u32 s = atomicAdd(&cnt_s[rowA], 1u); if (s < CMAX) { candD[rowA * CMAX + s] = d1A; candC[rowA * CMAX + s] = (u32)(c + 1); } }
                if (d0B <= thB) { u32 s = atomicAdd(&cnt_s[rowB], 1u); if (s < CMAX) { candD[rowB * CMAX + s] = d0B; candC[rowB * CMAX + s] = (u32)c; } }
                if (d1B <= thB) { u32 s = atomicAdd(&cnt_s[rowB], 1u); if (s < CMAX) { candD[rowB * CMAX + s] = d1B; candC[rowB * CMAX + s] = (u32)(c + 1); } }
            }
        }
    }

    __syncthreads();   // phase-1 complete: bestS/cand/cnt final

    // ---- phase-2: exact fp32 rescore of candidates (warp w -> 8 pixels) ----
    for (int i = 0; i < 8; ++i) {
        int px = wid * 8 + i;
        u32 c = cnt_s[px];
        float M = KEPS * sqrtf(znorm[px] * emax2);
        float th = unfkey((u32)(bestS[px] >> 32)) + 2.f * M;
        ull best = ~0ull;
        if (c <= CMAX) {
            for (u32 j = 0; j < c; ++j) {
                if (candD[px * CMAX + j] <= th) {
                    u32 cc = candC[px * CMAX + j];
                    float d = hh_s[cc] - rescore_dot(ZH, ZL, emb, px, (int)cc, lane);
                    ull key = ((ull)fkey(d) << 32) | cc;
                    if (key < best) best = key;
                }
            }
        } else {
            for (int cc = 0; cc < 512; ++cc) {      // overflow fallback: full rescan
                float d = hh_s[cc] - rescore_dot(ZH, ZL, emb, px, cc, lane);
                ull key = ((ull)fkey(d) << 32) | (u32)cc;
                if (key < best) best = key;
            }
        }
        if (lane == 0) fidx[px] = (u32)best;
    }

    __syncthreads();   // fidx final; Z planes reusable as gather staging

    // ---- gather winning rows into Qs[c][px], then coalesced write ----
    {
        int px = tid >> 2, qu = tid & 3;
        u32 idx = fidx[px];
        const float* er = emb + (size_t)idx * 128 + 32 * qu;
        float* Qs = SMF;
        #pragma unroll
        for (int i = 0; i < 8; ++i) {
            float4 v = *(const float4*)(er + 4 * i);
            int c = 32 * qu + 4 * i;
            Qs[(c + 0) * QS_STRIDE + px] = v.x;
            Qs[(c + 1) * QS_STRIDE + px] = v.y;
            Qs[(c + 2) * QS_STRIDE + px] = v.z;
            Qs[(c + 3) * QS_STRIDE + px] = v.w;
        }
    }
    __syncthreads();
    {
        int r = tid >> 1, half = tid & 1;           // 128 ch x 2 halves of 32px
        float* orow = out + (size_t)b * 128 * 4096 + (size_t)r * 4096 + p0 + 32 * half;
        const float* qrow = SMF + r * QS_STRIDE + 32 * half;
        #pragma unroll
        for (int i = 0; i < 8; ++i)
            *(float4*)(orow + 4 * i) = *(const float4*)(qrow + 4 * i);
    }
}

extern "C" void kernel_launch(void* const* d_in, const int* in_sizes, int n_in,
                              void* d_out, int out_size) {
    const float* z   = (const float*)d_in[0];   // (32,128,64,64) fp32
    const float* emb = (const float*)d_in[1];   // (512,128) fp32
    float* out = (float*)d_out;

    cudaFuncSetAttribute(vq_mma_kernel,
                         cudaFuncAttributeMaxDynamicSharedMemorySize, SMEM_BYTES);

    vq_prep<<<64, 256>>>(emb);
    vq_mma_kernel<<<2048, 256, SMEM_BYTES>>>(z, emb, out);
}

// round 10
// speedup vs baseline: 1.6157x; 1.2546x over previous
#include <cuda_runtime.h>
#include <cuda_fp16.h>
#include <cstdint>

typedef unsigned long long ull;
typedef unsigned int u32;

// ---------------- global scratch (static, no allocs) ----------------
// Bh fragment image for direct LDG.128:
//   uint4 index: (((ks*2+h)*4+cg)*4+np)*32 + lane   (lane = q*4+jj)
//   components: [n=2np b0, n=2np b1, n=2np+1 b0, n=2np+1 b1]
//   b0 = kpair jj, b1 = kpair jj+4 of k-group ks; code = h*256+cg*64+8n+q
__device__ __align__(16) u32 g_EimgH[32768];     // 128KB
__device__ float g_hhalf[512];     // 0.5*||e_c||^2 (fp32)
__device__ int g_emax2bits;        // max ||e_c||^2 as float bits (zero-init)

#define KEPS 1.25e-3f
#define CMAX 16
#define ZSTR 70

__device__ __forceinline__ u32 packsplit_hi(float v0, float v1, float& r0, float& r1) {
    __half h0 = __float2half_rn(v0), h1 = __float2half_rn(v1);
    r0 = v0 - __half2float(h0);
    r1 = v1 - __half2float(h1);
    return (u32)__half_as_ushort(h0) | ((u32)__half_as_ushort(h1) << 16);
}
__device__ __forceinline__ u32 pack_lo(float r0, float r1) {
    __half l0 = __float2half_rn(r0), l1 = __float2half_rn(r1);
    return (u32)__half_as_ushort(l0) | ((u32)__half_as_ushort(l1) << 16);
}
__device__ __forceinline__ unsigned fkey(float f) {   // monotonic float->uint
    unsigned u = __float_as_uint(f);
    return (u & 0x80000000u) ? ~u : (u | 0x80000000u);
}
__device__ __forceinline__ float unfkey(u32 k) {
    u32 u = (k & 0x80000000u) ? (k & 0x7fffffffu) : ~k;
    return __uint_as_float(u);
}
__device__ __forceinline__ void mma16(float* c, u32 a0, u32 a1, u32 a2, u32 a3,
                                      u32 b0, u32 b1) {
    asm("mma.sync.aligned.m16n8k16.row.col.f32.f16.f16.f32 "
        "{%0,%1,%2,%3}, {%4,%5,%6,%7}, {%8,%9}, {%0,%1,%2,%3};"
        : "+f"(c[0]), "+f"(c[1]), "+f"(c[2]), "+f"(c[3])
        : "r"(a0), "r"(a1), "r"(a2), "r"(a3), "r"(b0), "r"(b1));
}

// ---------------- prep: n-paired Bh fragment image + norms ----------------
__global__ void vq_prep(const float* __restrict__ emb) {
    int t = blockIdx.x * blockDim.x + threadIdx.x;
    int nt = gridDim.x * blockDim.x;
    for (int i = t; i < 512 * 64; i += nt) {       // (code, kpair)
        int code = i >> 6, p = i & 63;
        float v0 = emb[code * 128 + 2 * p], v1 = emb[code * 128 + 2 * p + 1];
        float r0, r1;
        u32 hi = packsplit_hi(v0, v1, r0, r1);
        int ks = p >> 3, pp = p & 7, jj = pp & 3, s = pp >> 2;
        int h = code >> 8, c8 = code & 255;
        int cg = c8 >> 6, rem = c8 & 63, n = rem >> 3, q = rem & 7;
        int np = n >> 1, no = n & 1;
        int idx = ((((ks * 2 + h) * 4 + cg) * 4 + np) * 32 + q * 4 + jj) * 4 + no * 2 + s;
        g_EimgH[idx] = hi;
    }
    if (t < 512) {
        const float* row = emb + t * 128;
        float s2 = 0.f;
        #pragma unroll 4
        for (int c = 0; c < 128; ++c) { float v = row[c]; s2 += v * v; }
        g_hhalf[t] = 0.5f * s2;
        atomicMax(&g_emax2bits, __float_as_int(s2));
    }
}

// ---------------- main kernel ----------------
// SMEM u32 offsets (64-px CTA), Z row stride 70:
#define ZHOFF  0          // 64 x 70
#define ZLOFF  4480       // 64 x 70
#define HHOFF  8960       // 512 floats
#define ZNOFF  9472       // 64 floats
#define BSTOFF 9536       // 64 u32 (fkey bits)
#define CDOFF  9600       // 64 x 16 floats
#define CCOFF  10624      // 64 x 16 u32
#define CNTOFF 11648      // 64 u32
#define FIOFF  11712      // 64 u32
#define SMEM_BYTES (11776 * 4)
#define QS_STRIDE 68

__device__ __forceinline__ float rescore_dot(const u32* __restrict__ ZH,
                                             const u32* __restrict__ ZL,
                                             const float* __restrict__ emb,
                                             int px, int cc, int lane) {
    int p0 = 2 * lane, p1 = p0 + 1;
    int col0 = (p0 >> 3) * 8 + 2 * (p0 & 3) + ((p0 >> 2) & 1);
    int col1 = (p1 >> 3) * 8 + 2 * (p1 & 3) + ((p1 >> 2) & 1);
    const u32* zh = ZH + px * ZSTR;
    const u32* zl = ZL + px * ZSTR;
    float2 a0 = __half22float2(*(const __half2*)&zh[col0]);
    float2 b0 = __half22float2(*(const __half2*)&zl[col0]);
    float2 a1 = __half22float2(*(const __half2*)&zh[col1]);
    float2 b1 = __half22float2(*(const __half2*)&zl[col1]);
    float4 e = *(const float4*)(emb + (size_t)cc * 128 + 4 * lane);
    float part = (a0.x + b0.x) * e.x + (a0.y + b0.y) * e.y
               + (a1.x + b1.x) * e.z + (a1.y + b1.y) * e.w;
    #pragma unroll
    for (int d = 16; d; d >>= 1) part += __shfl_xor_sync(0xffffffffu, part, d);
    return part;
}

__global__ __launch_bounds__(256, 2)
void vq_mma_kernel(const float* __restrict__ z, const float* __restrict__ emb,
                   float* __restrict__ out) {
    extern __shared__ float SMF[];
    u32* ZU = (u32*)SMF;
    const u32* ZH = ZU + ZHOFF;
    const u32* ZL = ZU + ZLOFF;
    float* hh_s = SMF + HHOFF;
    float* znorm = SMF + ZNOFF;
    u32* bestB = ZU + BSTOFF;
    float* candD = SMF + CDOFF;
    u32* candC = ZU + CCOFF;
    u32* cnt_s = ZU + CNTOFF;
    u32* fidx = ZU + FIOFF;

    const int tid = threadIdx.x;
    const int wid = tid >> 5, lane = tid & 31;
    const int jj = lane & 3, q = lane >> 2;
    const int pg = wid & 1, cg = wid >> 1;          // 2 px-groups x 4 code-groups
    const int px0 = pg << 5;
    const int b = blockIdx.x >> 6;
    const int p0 = (blockIdx.x & 63) << 6;          // 64-px tile

    const float* zb = z + (size_t)b * 128 * 4096 + p0;

    hh_s[tid] = g_hhalf[tid];
    hh_s[tid + 256] = g_hhalf[tid + 256];
    if (tid < 64) { bestB[tid] = 0xFFFFFFFFu; znorm[tid] = 0.f; cnt_s[tid] = 0u; }
    __syncthreads();

    // ---- Z producer: fp16-split 64px x 128k into hi/lo planes + ||z||^2 ----
    {
        int px = tid & 63, kg = tid >> 6;           // 4 groups x 16 kpairs
        u32* Zh = ZU + ZHOFF + px * ZSTR;
        u32* Zl = ZU + ZLOFF + px * ZSTR;
        float s = 0.f;
        #pragma unroll
        for (int pi = 0; pi < 16; ++pi) {
            int p = kg * 16 + pi;
            float v0 = zb[(size_t)(2 * p) * 4096 + px];
            float v1 = zb[(size_t)(2 * p + 1) * 4096 + px];
            float r0, r1;
            u32 hi = packsplit_hi(v0, v1, r0, r1);
            u32 lo = pack_lo(r0, r1);
            int col = (p >> 3) * 8 + 2 * (p & 3) + ((p >> 2) & 1);
            Zh[col] = hi;
            Zl[col] = lo;
            s += v0 * v0 + v1 * v1;
        }
        atomicAdd(&znorm[px], s);
    }
    __syncthreads();

    const float emax2 = __int_as_float(g_emax2bits);
    const u32* rA0 = ZH + (px0 + q) * ZSTR;
    const u32* rA1 = ZH + (px0 + q + 8) * ZSTR;
    const u32* rA2 = ZH + (px0 + q + 16) * ZSTR;
    const u32* rA3 = ZH + (px0 + q + 24) * ZSTR;

    for (int h = 0; h < 2; ++h) {
        float acc[2][8][4];
        #pragma unroll
        for (int m = 0; m < 2; ++m)
            #pragma unroll
            for (int n = 0; n < 8; ++n)
                #pragma unroll
                for (int r = 0; r < 4; ++r) acc[m][n][r] = 0.f;

        #pragma unroll
        for (int ks = 0; ks < 8; ++ks) {
            const int ao = ks * 8 + 2 * jj;
            uint2 a0 = *(const uint2*)(rA0 + ao);
            uint2 a1 = *(const uint2*)(rA1 + ao);
            uint2 a2 = *(const uint2*)(rA2 + ao);
            uint2 a3 = *(const uint2*)(rA3 + ao);
            const uint4* e4 = (const uint4*)g_EimgH
                              + (size_t)(((ks * 2 + h) * 4 + cg) * 4) * 32 + lane;
            #pragma unroll
            for (int np = 0; np < 4; ++np) {
                uint4 B = __ldg(e4 + np * 32);
                mma16(acc[0][2 * np],     a0.x, a1.x, a0.y, a1.y, B.x, B.y);
                mma16(acc[1][2 * np],     a2.x, a3.x, a2.y, a3.y, B.x, B.y);
                mma16(acc[0][2 * np + 1], a0.x, a1.x, a0.y, a1.y, B.z, B.w);
                mma16(acc[1][2 * np + 1], a2.x, a3.x, a2.y, a3.y, B.z, B.w);
            }
        }

        // ---- phase-1 epilogue: float-only min + candidate collection ----
        #pragma unroll
        for (int m = 0; m < 2; ++m) {
            int rowA = px0 + 16 * m + q, rowB = rowA + 8;
            float mnA = 1e30f, mnB = 1e30f;
            #pragma unroll
            for (int n = 0; n < 8; ++n) {
                int c = h * 256 + cg * 64 + 8 * n + 2 * jj;
                float hc0 = hh_s[c], hc1 = hh_s[c + 1];
                mnA = fminf(mnA, fminf(hc0 - acc[m][n][0], hc1 - acc[m][n][1]));
                mnB = fminf(mnB, fminf(hc0 - acc[m][n][2], hc1 - acc[m][n][3]));
            }
            #pragma unroll
            for (int d = 1; d <= 2; d <<= 1) {
                mnA = fminf(mnA, __shfl_xor_sync(0xffffffffu, mnA, d));
                mnB = fminf(mnB, __shfl_xor_sync(0xffffffffu, mnB, d));
            }
            u32 kA = fkey(mnA), kB = fkey(mnB);
            u32 curA = *(volatile u32*)&bestB[rowA];
            u32 curB = *(volatile u32*)&bestB[rowB];
            float MA = KEPS * sqrtf(znorm[rowA] * emax2);
            float MB = KEPS * sqrtf(znorm[rowB] * emax2);
            float thA = unfkey(kA < curA ? kA : curA) + 2.f * MA;
            float thB = unfkey(kB < curB ? kB : curB) + 2.f * MB;
            if (jj == 0) {
                atomicMin(&bestB[rowA], kA);
                atomicMin(&bestB[rowB], kB);
            }
            #pragma unroll
            for (int n = 0; n < 8; ++n) {
                int c = h * 256 + cg * 64 + 8 * n + 2 * jj;
                float hc0 = hh_s[c], hc1 = hh_s[c + 1];
                float d0A = hc0 - acc[m][n][0], d1A = hc1 - acc[m][n][1];
                float d0B = hc0 - acc[m][n][2], d1B = hc1 - acc[m][n][3];
                if (d0A <= thA) { u32 s = atomicAdd(&cnt_s[rowA], 1u); if (s < CMAX) { candD[rowA * CMAX + s] = d0A; candC[rowA * CMAX + s] = (u32)c; } }
                if (d1A <= thA) { u32 s = atomicAdd(&cnt_s[rowA], 1u); if (s < CMAX) { candD[rowA * CMAX + s] = d1A; candC[rowA * CMAX + s] = (u32)(c + 1); } }
                if (d0B <= thB) { u32 s = atomicAdd(&cnt_s[rowB], 1u); if (s < CMAX) { candD[rowB * CMAX + s] = d0B; candC[rowB * CMAX + s] = (u32)c; } }
                if (d1B <= thB) { u32 s = atomicAdd(&cnt_s[rowB], 1u); if (s < CMAX) { candD[rowB * CMAX + s] = d1B; candC[rowB * CMAX + s] = (u32)(c + 1); } }
            }
        }
    }

    __syncthreads();   // phase-1 complete: bestB/cand/cnt final

    // ---- phase-2: exact fp32 rescore of candidates (warp w -> 8 pixels) ----
    for (int i = 0; i < 8; ++i) {
        int px = wid * 8 + i;
        u32 c = cnt_s[px];
        float M = KEPS * sqrtf(znorm[px] * emax2);
        float th = unfkey(bestB[px]) + 2.f * M;
        ull best = ~0ull;
        if (c <= CMAX) {
            for (u32 j = 0; j < c; ++j) {
                if (candD[px * CMAX + j] <= th) {
                    u32 cc = candC[px * CMAX + j];
                    float d = hh_s[cc] - rescore_dot(ZH, ZL, emb, px, (int)cc, lane);
                    ull key = ((ull)fkey(d) << 32) | cc;
                    if (key < best) best = key;
                }
            }
        } else {
            for (int cc = 0; cc < 512; ++cc) {      // overflow fallback: full rescan
                float d = hh_s[cc] - rescore_dot(ZH, ZL, emb, px, cc, lane);
                ull key = ((ull)fkey(d) << 32) | (u32)cc;
                if (key < best) best = key;
            }
        }
        if (lane == 0) fidx[px] = (u32)best;
    }

    __syncthreads();   // fidx final; Z planes reusable as gather staging

    // ---- gather winning rows into Qs[c][px], then coalesced write ----
    {
        int px = tid >> 2, qu = tid & 3;
        u32 idx = fidx[px];
        const float* er = emb + (size_t)idx * 128 + 32 * qu;
        float* Qs = SMF;
        #pragma unroll
        for (int i = 0; i < 8; ++i) {
            float4 v = *(const float4*)(er + 4 * i);
            int c = 32 * qu + 4 * i;
            Qs[(c + 0) * QS_STRIDE + px] = v.x;
            Qs[(c + 1) * QS_STRIDE + px] = v.y;
            Qs[(c + 2) * QS_STRIDE + px] = v.z;
            Qs[(c + 3) * QS_STRIDE + px] = v.w;
        }
    }
    __syncthreads();
    {
        int r = tid >> 1, half = tid & 1;           // 128 ch x 2 halves of 32px
        float* orow = out + (size_t)b * 128 * 4096 + (size_t)r * 4096 + p0 + 32 * half;
        const float* qrow = SMF + r * QS_STRIDE + 32 * half;
        #pragma unroll
        for (int i = 0; i < 8; ++i)
            *(float4*)(orow + 4 * i) = *(const float4*)(qrow + 4 * i);
    }
}

extern "C" void kernel_launch(void* const* d_in, const int* in_sizes, int n_in,
                              void* d_out, int out_size) {
    const float* z   = (const float*)d_in[0];   // (32,128,64,64) fp32
    const float* emb = (const float*)d_in[1];   // (512,128) fp32
    float* out = (float*)d_out;

    cudaFuncSetAttribute(vq_mma_kernel,
                         cudaFuncAttributeMaxDynamicSharedMemorySize, SMEM_BYTES);

    vq_prep<<<64, 256>>>(emb);
    vq_mma_kernel<<<2048, 256, SMEM_BYTES>>>(z, emb, out);
}

// round 12
// speedup vs baseline: 1.6584x; 1.0264x over previous
#include <cuda_runtime.h>
#include <cuda_fp16.h>
#include <cstdint>

typedef unsigned long long ull;
typedef unsigned int u32;

// ---------------- global scratch (static, no allocs) ----------------
// Bh fragment image for direct LDG.128 (unchanged from round 10):
//   uint4 index: (((ks*2+h)*4+cg)*4+np)*32 + lane   (lane = q*4+jj)
__device__ __align__(16) u32 g_EimgH[32768];     // 128KB
__device__ float g_hhalf[512];     // 0.5*||e_c||^2 (fp32)
__device__ int g_emax2bits;        // max ||e_c||^2 as float bits (zero-init)

#define KEPS 1.25e-3f
#define CMAX 16
#define ZRS 144                    // Z plane row stride (u32); 32 rows per plane

__device__ __forceinline__ u32 packsplit_hi(float v0, float v1, float& r0, float& r1) {
    __half h0 = __float2half_rn(v0), h1 = __float2half_rn(v1);
    r0 = v0 - __half2float(h0);
    r1 = v1 - __half2float(h1);
    return (u32)__half_as_ushort(h0) | ((u32)__half_as_ushort(h1) << 16);
}
__device__ __forceinline__ u32 pack_lo(float r0, float r1) {
    __half l0 = __float2half_rn(r0), l1 = __float2half_rn(r1);
    return (u32)__half_as_ushort(l0) | ((u32)__half_as_ushort(l1) << 16);
}
__device__ __forceinline__ unsigned fkey(float f) {   // monotonic float->uint
    unsigned u = __float_as_uint(f);
    return (u & 0x80000000u) ? ~u : (u | 0x80000000u);
}
__device__ __forceinline__ float unfkey(u32 k) {
    u32 u = (k & 0x80000000u) ? (k & 0x7fffffffu) : ~k;
    return __uint_as_float(u);
}
__device__ __forceinline__ void mma16(float* c, u32 a0, u32 a1, u32 a2, u32 a3,
                                      u32 b0, u32 b1) {
    asm("mma.sync.aligned.m16n8k16.row.col.f32.f16.f16.f32 "
        "{%0,%1,%2,%3}, {%4,%5,%6,%7}, {%8,%9}, {%0,%1,%2,%3};"
        : "+f"(c[0]), "+f"(c[1]), "+f"(c[2]), "+f"(c[3])
        : "r"(a0), "r"(a1), "r"(a2), "r"(a3), "r"(b0), "r"(b1));
}

// ---------------- prep: n-paired Bh fragment image + norms (unchanged) ----------------
__global__ void vq_prep(const float* __restrict__ emb) {
    int t = blockIdx.x * blockDim.x + threadIdx.x;
    int nt = gridDim.x * blockDim.x;
    for (int i = t; i < 512 * 64; i += nt) {       // (code, kpair)
        int code = i >> 6, p = i & 63;
        float v0 = emb[code * 128 + 2 * p], v1 = emb[code * 128 + 2 * p + 1];
        float r0, r1;
        u32 hi = packsplit_hi(v0, v1, r0, r1);
        int ks = p >> 3, pp = p & 7, jj = pp & 3, s = pp >> 2;
        int h = code >> 8, c8 = code & 255;
        int cg = c8 >> 6, rem = c8 & 63, n = rem >> 3, q = rem & 7;
        int np = n >> 1, no = n & 1;
        int idx = ((((ks * 2 + h) * 4 + cg) * 4 + np) * 32 + q * 4 + jj) * 4 + no * 2 + s;
        g_EimgH[idx] = hi;
    }
    if (t < 512) {
        const float* row = emb + t * 128;
        float s2 = 0.f;
        #pragma unroll 4
        for (int c = 0; c < 128; ++c) { float v = row[c]; s2 += v * v; }
        g_hhalf[t] = 0.5f * s2;
        atomicMax(&g_emax2bits, __float_as_int(s2));
    }
}

// ---------------- main kernel ----------------
// Z plane layout (pair-interleaved, mma-ordered quads):
//   row r = (px>>4)*8 + (px&7), s = (px>>3)&1.
//   quad j of k-group ks holds kpairs {ks*8+j, ks*8+j+4}:
//     uint4 = [Z(px_a, j), Z(px_b, j), Z(px_a, j+4), Z(px_b, j+4)]
//   at u32 pos: r*ZRS + (ks*4 + ((j + (r>>1)) & 3))*4 + half*2 + s
//   (for kpair p: ks=p>>3, c=p&7, j=c&3, half=c>>2)
#define ZHOFF  0          // 32 x 144
#define ZLOFF  4608       // 32 x 144
#define HHOFF  9216       // 512 floats
#define ZNOFF  9728       // 64 floats
#define BSTOFF 9792       // 64 u32 (fkey bits)
#define CDOFF  9856       // 64 x 16 floats
#define CCOFF  10880      // 64 x 16 u32
#define CNTOFF 11904      // 64 u32
#define FIOFF  11968      // 64 u32
#define SMEM_BYTES (12032 * 4)
#define QS_STRIDE 68

__device__ __forceinline__ u32 zpos(int px, int p) {   // u32 index within a plane
    int r = (px >> 4) * 8 + (px & 7), s = (px >> 3) & 1;
    int ks = p >> 3, c = p & 7;
    return (u32)(r * ZRS + (ks * 4 + (((c & 3) + (r >> 1)) & 3)) * 4 + (c >> 2) * 2 + s);
}

__device__ __forceinline__ float rescore_dot(const u32* __restrict__ ZH,
                                             const u32* __restrict__ ZL,
                                             const float* __restrict__ emb,
                                             int px, int cc, int lane) {
    int p0 = 2 * lane, p1 = p0 + 1;
    u32 o0 = zpos(px, p0), o1 = zpos(px, p1);
    float2 a0 = __half22float2(*(const __half2*)&ZH[o0]);
    float2 b0 = __half22float2(*(const __half2*)&ZL[o0]);
    float2 a1 = __half22float2(*(const __half2*)&ZH[o1]);
    float2 b1 = __half22float2(*(const __half2*)&ZL[o1]);
    float4 e = *(const float4*)(emb + (size_t)cc * 128 + 4 * lane);
    float part = (a0.x + b0.x) * e.x + (a0.y + b0.y) * e.y
               + (a1.x + b1.x) * e.z + (a1.y + b1.y) * e.w;
    #pragma unroll
    for (int d = 16; d; d >>= 1) part += __shfl_xor_sync(0xffffffffu, part, d);
    return part;
}

__global__ __launch_bounds__(256, 2)
void vq_mma_kernel(const float* __restrict__ z, const float* __restrict__ emb,
                   float* __restrict__ out) {
    extern __shared__ float SMF[];
    u32* ZU = (u32*)SMF;
    const u32* ZH = ZU + ZHOFF;
    const u32* ZL = ZU + ZLOFF;
    float* hh_s = SMF + HHOFF;
    float* znorm = SMF + ZNOFF;
    u32* bestB = ZU + BSTOFF;
    float* candD = SMF + CDOFF;
    u32* candC = ZU + CCOFF;
    u32* cnt_s = ZU + CNTOFF;
    u32* fidx = ZU + FIOFF;

    const int tid = threadIdx.x;
    const int wid = tid >> 5, lane = tid & 31;
    const int jj = lane & 3, q = lane >> 2;
    const int pg = wid & 1, cg = wid >> 1;          // 2 px-groups x 4 code-groups
    const int px0 = pg << 5;
    const int b = blockIdx.x >> 6;
    const int p0 = (blockIdx.x & 63) << 6;          // 64-px tile

    const float* zb = z + (size_t)b * 128 * 4096 + p0;

    hh_s[tid] = g_hhalf[tid];
    hh_s[tid + 256] = g_hhalf[tid + 256];
    if (tid < 64) { bestB[tid] = 0xFFFFFFFFu; znorm[tid] = 0.f; cnt_s[tid] = 0u; }
    __syncthreads();

    // ---- Z producer: thread = (row r, k-group kg); wide STS.128 writes ----
    {
        int r = tid & 31, kg = tid >> 5;
        int px_a = (r >> 3) * 16 + (r & 7);         // s = 0
        int px_b = px_a + 8;                        // s = 1
        u32 hiA[8], loA[8], hiB[8], loB[8];
        float sa = 0.f, sb = 0.f;
        #pragma unroll
        for (int c = 0; c < 8; ++c) {               // kpair p = kg*8+c
            const float* zc = zb + (size_t)(kg * 8 + c) * 2 * 4096;
            float va0 = zc[px_a], va1 = zc[4096 + px_a];
            float vb0 = zc[px_b], vb1 = zc[4096 + px_b];
            float r0, r1;
            hiA[c] = packsplit_hi(va0, va1, r0, r1);
            loA[c] = pack_lo(r0, r1);
            sa += va0 * va0 + va1 * va1;
            hiB[c] = packsplit_hi(vb0, vb1, r0, r1);
            loB[c] = pack_lo(r0, r1);
            sb += vb0 * vb0 + vb1 * vb1;
        }
        u32* Zh = ZU + ZHOFF + r * ZRS;
        u32* Zl = ZU + ZLOFF + r * ZRS;
        int rs = r >> 1;
        #pragma unroll
        for (int j = 0; j < 4; ++j) {               // quad j: kpairs {j, j+4}
            int pq = (kg * 4 + ((j + rs) & 3)) * 4;
            *(uint4*)(Zh + pq) = make_uint4(hiA[j], hiB[j], hiA[j + 4], hiB[j + 4]);
            *(uint4*)(Zl + pq) = make_uint4(loA[j], loB[j], loA[j + 4], loB[j + 4]);
        }
        atomicAdd(&znorm[px_a], sa);
        atomicAdd(&znorm[px_b], sb);
    }
    __syncthreads();

    const float emax2 = __int_as_float(g_emax2bits);
    const u32* Arow0 = ZH + ((pg * 2 + 0) * 8 + q) * ZRS;   // m=0: px0+q / px0+q+8
    const u32* Arow1 = ZH + ((pg * 2 + 1) * 8 + q) * ZRS;   // m=1: px0+16+q / +24
    const int qsw = (q >> 1) & 3;

    for (int h = 0; h < 2; ++h) {
        float acc[2][8][4];
        #pragma unroll
        for (int m = 0; m < 2; ++m)
            #pragma unroll
            for (int n = 0; n < 8; ++n)
                #pragma unroll
                for (int r = 0; r < 4; ++r) acc[m][n][r] = 0.f;

        #pragma unroll
        for (int ks = 0; ks < 8; ++ks) {
            int pq = (ks * 4 + ((jj + qsw) & 3)) * 4;
            uint4 A0 = *(const uint4*)(Arow0 + pq);   // [a0 a1 a2 a3] mma order
            uint4 A1 = *(const uint4*)(Arow1 + pq);
            const uint4* e4 = (const uint4*)g_EimgH
                              + (size_t)(((ks * 2 + h) * 4 + cg) * 4) * 32 + lane;
            #pragma unroll
            for (int np = 0; np < 4; ++np) {
                uint4 B = __ldg(e4 + np * 32);
                mma16(acc[0][2 * np],     A0.x, A0.y, A0.z, A0.w, B.x, B.y);
                mma16(acc[1][2 * np],     A1.x, A1.y, A1.z, A1.w, B.x, B.y);
                mma16(acc[0][2 * np + 1], A0.x, A0.y, A0.z, A0.w, B.z, B.w);
                mma16(acc[1][2 * np + 1], A1.x, A1.y, A1.z, A1.w, B.z, B.w);
            }
        }

        // ---- phase-1 epilogue: float-only min + candidate collection ----
        #pragma unroll
        for (int m = 0; m < 2; ++m) {
            int rowA = px0 + 16 * m + q, rowB = rowA + 8;
            float mnA = 1e30f, mnB = 1e30f;
            #pragma unroll
            for (int n = 0; n < 8; ++n) {
                int c = h * 256 + cg * 64 + 8 * n + 2 * jj;
                float hc0 = hh_s[c], hc1 = hh_s[c + 1];
                mnA = fminf(mnA, fminf(hc0 - acc[m][n][0], hc1 - acc[m][n][1]));
                mnB = fminf(mnB, fminf(hc0 - acc[m][n][2], hc1 - acc[m][n][3]));
            }
            #pragma unroll
            for (int d = 1; d <= 2; d <<= 1) {
                mnA = fminf(mnA, __shfl_xor_sync(0xffffffffu, mnA, d));
                mnB = fminf(mnB, __shfl_xor_sync(0xffffffffu, mnB, d));
            }
            u32 kA = fkey(mnA), kB = fkey(mnB);
            u32 curA = *(volatile u32*)&bestB[rowA];
            u32 curB = *(volatile u32*)&bestB[rowB];
            float MA = KEPS * sqrtf(znorm[rowA] * emax2);
            float MB = KEPS * sqrtf(znorm[rowB] * emax2);
            float thA = unfkey(kA < curA ? kA : curA) + 2.f * MA;
            float thB = unfkey(kB < curB ? kB : curB) + 2.f * MB;
            if (jj == 0) {
                atomicMin(&bestB[rowA], kA);
                atomicMin(&bestB[rowB], kB);
            }
            #pragma unroll
            for (int n = 0; n < 8; ++n) {
                int c = h * 256 + cg * 64 + 8 * n + 2 * jj;
                float hc0 = hh_s[c], hc1 = hh_s[c + 1];
                float d0A = hc0 - acc[m][n][0], d1A = hc1 - acc[m][n][1];
                float d0B = hc0 - acc[m][n][2], d1B = hc1 - acc[m][n][3];
                if (d0A <= thA) { u32 s = atomicAdd(&cnt_s[rowA], 1u); if (s < CMAX) { candD[rowA * CMAX + s] = d0A; candC[rowA * CMAX + s] = (u32)c; } }
                if (d1A <= thA) { u32 s = atomicAdd(&cnt_s[rowA], 1u); if (s < CMAX) { candD[rowA * CMAX + s] = d1A; candC[rowA * CMAX + s] = (u32)(c + 1); } }
                if (d0B <= thB) { u32 s = atomicAdd(&cnt_s[rowB], 1u); if (s < CMAX) { candD[rowB * CMAX + s] = d0B; candC[rowB * CMAX + s] = (u32)c; } }
                if (d1B <= thB) { u32 s = atomicAdd(&cnt_s[rowB], 1u); if (s < CMAX) { candD[rowB * CMAX + s] = d1B; candC[rowB * CMAX + s] = (u32)(c + 1); } }
            }
        }
    }

    __syncthreads();   // phase-1 complete: bestB/cand/cnt final

    // ---- phase-2: exact fp32 rescore of candidates (warp w -> 8 pixels) ----
    for (int i = 0; i < 8; ++i) {
        int px = wid * 8 + i;
        u32 c = cnt_s[px];
        float M = KEPS * sqrtf(znorm[px] * emax2);
        float th = unfkey(bestB[px]) + 2.f * M;
        ull best = ~0ull;
        if (c <= CMAX) {
            for (u32 j = 0; j < c; ++j) {
                if (candD[px * CMAX + j] <= th) {
                    u32 cc = candC[px * CMAX + j];
                    float d = hh_s[cc] - rescore_dot(ZH, ZL, emb, px, (int)cc, lane);
                    ull key = ((ull)fkey(d) << 32) | cc;
                    if (key < best) best = key;
                }
            }
        } else {
            for (int cc = 0; cc < 512; ++cc) {      // overflow fallback: full rescan
                float d = hh_s[cc] - rescore_dot(ZH, ZL, emb, px, cc, lane);
                ull key = ((ull)fkey(d) << 32) | (u32)cc;
                if (key < best) best = key;
            }
        }
        if (lane == 0) fidx[px] = (u32)best;
    }

    __syncthreads();   // fidx final; Z planes reusable as gather staging

    // ---- gather winning rows into Qs[c][px], then coalesced write ----
    {
        int px = tid >> 2, qu = tid & 3;
        u32 idx = fidx[px];
        const float* er = emb + (size_t)idx * 128 + 32 * qu;
        float* Qs = SMF;
        #pragma unroll
        for (int i = 0; i < 8; ++i) {
            float4 v = *(const float4*)(er + 4 * i);
            int c = 32 * qu + 4 * i;
            Qs[(c + 0) * QS_STRIDE + px] = v.x;
            Qs[(c + 1) * QS_STRIDE + px] = v.y;
            Qs[(c + 2) * QS_STRIDE + px] = v.z;
            Qs[(c + 3) * QS_STRIDE + px] = v.w;
        }
    }
    __syncthreads();
    {
        int r = tid >> 1, half = tid & 1;           // 128 ch x 2 halves of 32px
        float* orow = out + (size_t)b * 128 * 4096 + (size_t)r * 4096 + p0 + 32 * half;
        const float* qrow = SMF + r * QS_STRIDE + 32 * half;
        #pragma unroll
        for (int i = 0; i < 8; ++i)
            *(float4*)(orow + 4 * i) = *(const float4*)(qrow + 4 * i);
    }
}

extern "C" void kernel_launch(void* const* d_in, const int* in_sizes, int n_in,
                              void* d_out, int out_size) {
    const float* z   = (const float*)d_in[0];   // (32,128,64,64) fp32
    const float* emb = (const float*)d_in[1];   // (512,128) fp32
    float* out = (float*)d_out;

    cudaFuncSetAttribute(vq_mma_kernel,
                         cudaFuncAttributeMaxDynamicSharedMemorySize, SMEM_BYTES);

    vq_prep<<<64, 256>>>(emb);
    vq_mma_kernel<<<2048, 256, SMEM_BYTES>>>(z, emb, out);
}